// round 1
// baseline (speedup 1.0000x reference)
#include <cuda_runtime.h>

#define NN 50000
#define EE 800000

// ---------------- scratch (static device globals; no allocs) ----------------
static __device__ float g_h[NN*64];      // GCN-transformed features
static __device__ float g_res[NN*64];    // residual branch
static __device__ float g_agg[NN*64];    // aggregation target (GCN then GAT)
static __device__ float g_xln[NN*64];    // post-GCN layernorm output
static __device__ float g_xg[NN*64];     // GAT-transformed features
static __device__ float g_xcur[NN*64];   // layer-0 output
static __device__ float g_deg[NN];
static __device__ float g_dinv[NN];
static __device__ float g_as[NN*4];
static __device__ float g_ad[NN*4];
static __device__ float g_s[NN*4];
static __device__ float g_eself[NN*4];
static __device__ float g_ealpha[EE*4];
static __device__ float g_ce[8];         // [0..3]=ce per head, [4]=mean(edge_attr)
static __device__ float g_easum;

// ---------------- helpers ----------------
__device__ __forceinline__ float siluf(float v) { return v * (1.f / (1.f + __expf(-v))); }
__device__ __forceinline__ float lrelu(float v) { return v >= 0.f ? v : 0.2f * v; }

__device__ __forceinline__ void red_add_v4(float* a, float x, float y, float z, float w) {
    asm volatile("red.global.add.v4.f32 [%0], {%1,%2,%3,%4};"
                 :: "l"(a), "f"(x), "f"(y), "f"(z), "f"(w) : "memory");
}

// ---------------- GEMMs ----------------
// y0 = x @ W0 (bias later), y1 = x @ W1 + b1. 32-row tile, 256 threads.
__global__ __launch_bounds__(256) void k_gemm_dual(
    const float* __restrict__ xin, const float* __restrict__ W0,
    const float* __restrict__ W1, const float* __restrict__ b1)
{
    const float* x = xin ? xin : g_xcur;
    __shared__ float xs[32*68];
    __shared__ float ws[2][64*68];
    int t = threadIdx.x;
    int row0 = blockIdx.x * 32;
    for (int i = t; i < 4096; i += 256) {
        int k = i >> 6, c = i & 63;
        ws[0][k*68+c] = W0[i];
        ws[1][k*68+c] = W1[i];
    }
    for (int i = t; i < 2048; i += 256) {
        int r = i >> 6, c = i & 63;
        xs[r*68+c] = (row0 + r < NN) ? x[(row0+r)*64 + c] : 0.f;
    }
    __syncthreads();
    int rg = t >> 4, g = t & 15, m = g >> 3, cb = (g & 7) * 8;
    const float* wp = ws[m];
    int r0 = rg*2, r1 = r0 + 1;
    float a0[8], a1[8];
    #pragma unroll
    for (int j = 0; j < 8; j++) { a0[j] = 0.f; a1[j] = 0.f; }
    #pragma unroll 16
    for (int k = 0; k < 64; k++) {
        float xv0 = xs[r0*68+k], xv1 = xs[r1*68+k];
        float w[8];
        *(float4*)&w[0] = *(const float4*)&wp[k*68+cb];
        *(float4*)&w[4] = *(const float4*)&wp[k*68+cb+4];
        #pragma unroll
        for (int j = 0; j < 8; j++) { a0[j] += xv0 * w[j]; a1[j] += xv1 * w[j]; }
    }
    float* y = m ? g_res : g_h;
    if (m) {
        #pragma unroll
        for (int j = 0; j < 8; j++) { float b = b1[cb+j]; a0[j] += b; a1[j] += b; }
    }
    if (row0 + r0 < NN) {
        *(float4*)&y[(row0+r0)*64+cb]   = *(float4*)&a0[0];
        *(float4*)&y[(row0+r0)*64+cb+4] = *(float4*)&a0[4];
    }
    if (row0 + r1 < NN) {
        *(float4*)&y[(row0+r1)*64+cb]   = *(float4*)&a1[0];
        *(float4*)&y[(row0+r1)*64+cb+4] = *(float4*)&a1[4];
    }
}

// g_xg = g_xln @ W (no bias). 64-row tile, 256 threads.
__global__ __launch_bounds__(256) void k_gemm_gat(const float* __restrict__ W)
{
    __shared__ float xs[64*68];
    __shared__ float ws[64*68];
    int t = threadIdx.x;
    int row0 = blockIdx.x * 64;
    for (int i = t; i < 4096; i += 256) {
        int k = i >> 6, c = i & 63;
        ws[k*68+c] = W[i];
    }
    for (int i = t; i < 4096; i += 256) {
        int r = i >> 6, c = i & 63;
        xs[r*68+c] = (row0 + r < NN) ? g_xln[(row0+r)*64 + c] : 0.f;
    }
    __syncthreads();
    int rg = t >> 3, cb = (t & 7) * 8;
    int r0 = rg*2, r1 = r0 + 1;
    float a0[8], a1[8];
    #pragma unroll
    for (int j = 0; j < 8; j++) { a0[j] = 0.f; a1[j] = 0.f; }
    #pragma unroll 16
    for (int k = 0; k < 64; k++) {
        float xv0 = xs[r0*68+k], xv1 = xs[r1*68+k];
        float w[8];
        *(float4*)&w[0] = *(const float4*)&ws[k*68+cb];
        *(float4*)&w[4] = *(const float4*)&ws[k*68+cb+4];
        #pragma unroll
        for (int j = 0; j < 8; j++) { a0[j] += xv0 * w[j]; a1[j] += xv1 * w[j]; }
    }
    if (row0 + r0 < NN) {
        *(float4*)&g_xg[(row0+r0)*64+cb]   = *(float4*)&a0[0];
        *(float4*)&g_xg[(row0+r0)*64+cb+4] = *(float4*)&a0[4];
    }
    if (row0 + r1 < NN) {
        *(float4*)&g_xg[(row0+r1)*64+cb]   = *(float4*)&a1[0];
        *(float4*)&g_xg[(row0+r1)*64+cb+4] = *(float4*)&a1[4];
    }
}

// ---------------- GCN ----------------
__global__ void k_deg_init() {
    int i = blockIdx.x*256 + threadIdx.x;
    if (i < NN) g_deg[i] = 1.f;          // self-loop weight
}
__global__ void k_deg_edge(const int* __restrict__ ei, const float* __restrict__ ew) {
    int e = blockIdx.x*256 + threadIdx.x;
    atomicAdd(&g_deg[ei[EE+e]], ew[e]);
}
__global__ void k_dinv() {
    int i = blockIdx.x*256 + threadIdx.x;
    if (i < NN) g_dinv[i] = rsqrtf(g_deg[i]);
}
__global__ void k_gcn_init() {
    int idx = blockIdx.x*256 + threadIdx.x;   // NN*64
    int i = idx >> 6;
    float dv = g_dinv[i];
    g_agg[idx] = g_h[idx] * dv * dv;          // self-loop contribution
}
__global__ void k_gcn_edge(const int* __restrict__ ei, const float* __restrict__ ew) {
    int idx = blockIdx.x*256 + threadIdx.x;   // EE*16
    int e = idx >> 4, ch = idx & 15;
    int s = ei[e], d = ei[EE+e];
    float nrm = g_dinv[s] * ew[e] * g_dinv[d];
    float4 v = *(const float4*)&g_h[s*64 + ch*4];
    red_add_v4(&g_agg[d*64 + ch*4], v.x*nrm, v.y*nrm, v.z*nrm, v.w*nrm);
}
// xln = LN(silu(agg + gcn_b) + res) ; warp per row
__global__ __launch_bounds__(256) void k_ln(
    const float* __restrict__ gb, const float* __restrict__ lg, const float* __restrict__ lb)
{
    int row = blockIdx.x*8 + (threadIdx.x >> 5);
    int lane = threadIdx.x & 31;
    float v0 = siluf(g_agg[row*64+lane]      + gb[lane])      + g_res[row*64+lane];
    float v1 = siluf(g_agg[row*64+lane+32]   + gb[lane+32])   + g_res[row*64+lane+32];
    float sum = v0 + v1;
    #pragma unroll
    for (int o = 16; o; o >>= 1) sum += __shfl_xor_sync(0xffffffffu, sum, o);
    float mu = sum * (1.f/64.f);
    float d0 = v0 - mu, d1 = v1 - mu;
    float vs = d0*d0 + d1*d1;
    #pragma unroll
    for (int o = 16; o; o >>= 1) vs += __shfl_xor_sync(0xffffffffu, vs, o);
    float inv = rsqrtf(vs * (1.f/64.f) + 1e-5f);
    g_xln[row*64+lane]    = d0 * inv * lg[lane]    + lb[lane];
    g_xln[row*64+lane+32] = d1 * inv * lg[lane+32] + lb[lane+32];
}

// ---------------- GAT ----------------
__global__ __launch_bounds__(256) void k_attdots(
    const float* __restrict__ asrc, const float* __restrict__ adst)
{
    int row = blockIdx.x*8 + (threadIdx.x >> 5);
    int lane = threadIdx.x & 31;
    float x0 = g_xg[row*64+lane], x1 = g_xg[row*64+lane+32];
    float s0 = x0*asrc[lane], s1 = x1*asrc[lane+32];
    float d0 = x0*adst[lane], d1 = x1*adst[lane+32];
    #pragma unroll
    for (int o = 8; o; o >>= 1) {
        s0 += __shfl_xor_sync(0xffffffffu, s0, o);
        s1 += __shfl_xor_sync(0xffffffffu, s1, o);
        d0 += __shfl_xor_sync(0xffffffffu, d0, o);
        d1 += __shfl_xor_sync(0xffffffffu, d1, o);
    }
    if ((lane & 15) == 0) {
        int h = lane >> 4;
        g_as[row*4 + h]     = s0;
        g_as[row*4 + 2 + h] = s1;
        g_ad[row*4 + h]     = d0;
        g_ad[row*4 + 2 + h] = d1;
    }
}
__global__ void k_zero() { g_easum = 0.f; }
__global__ void k_easum(const float* __restrict__ ea) {
    __shared__ float ss[8];
    float sum = 0.f;
    for (int i = blockIdx.x*blockDim.x + threadIdx.x; i < EE; i += gridDim.x*blockDim.x)
        sum += ea[i];
    #pragma unroll
    for (int o = 16; o; o >>= 1) sum += __shfl_xor_sync(0xffffffffu, sum, o);
    if ((threadIdx.x & 31) == 0) ss[threadIdx.x >> 5] = sum;
    __syncthreads();
    if (threadIdx.x < 8) {
        float v = ss[threadIdx.x];
        #pragma unroll
        for (int o = 4; o; o >>= 1) v += __shfl_xor_sync(0xffu, v, o);
        if (threadIdx.x == 0) atomicAdd(&g_easum, v);
    }
}
// ce[h] = sum_c We[h*16+c]*a_e[h*16+c]; ce[4] = mean(edge_attr)
__global__ void k_ce(const float* __restrict__ eww, const float* __restrict__ ae) {
    int lane = threadIdx.x;
    float p0 = eww[lane]*ae[lane];
    float p1 = eww[lane+32]*ae[lane+32];
    #pragma unroll
    for (int o = 8; o; o >>= 1) {
        p0 += __shfl_xor_sync(0xffffffffu, p0, o);
        p1 += __shfl_xor_sync(0xffffffffu, p1, o);
    }
    if ((lane & 15) == 0) {
        g_ce[lane >> 4]     = p0;
        g_ce[2 + (lane >> 4)] = p1;
    }
    if (lane == 0) g_ce[4] = g_easum * (1.f / EE);
}
// self-loop term initializes the softmax denominator
__global__ void k_sinit() {
    int idx = blockIdx.x*256 + threadIdx.x;
    if (idx < NN*4) {
        int h = idx & 3;
        float al = lrelu(g_as[idx] + g_ad[idx] + g_ce[4]*g_ce[h]);
        float p = __expf(fminf(al, 70.f));
        g_s[idx] = p;
        g_eself[idx] = p;
    }
}
__global__ void k_gatA(const int* __restrict__ ei, const float* __restrict__ ea) {
    int e = blockIdx.x*256 + threadIdx.x;
    int s = ei[e], d = ei[EE+e];
    float eav = ea[e];
    float4 av = *(const float4*)&g_as[s*4];
    float4 dv = *(const float4*)&g_ad[d*4];
    float4 ce = *(const float4*)&g_ce[0];
    float p0 = __expf(fminf(lrelu(av.x + dv.x + eav*ce.x), 70.f));
    float p1 = __expf(fminf(lrelu(av.y + dv.y + eav*ce.y), 70.f));
    float p2 = __expf(fminf(lrelu(av.z + dv.z + eav*ce.z), 70.f));
    float p3 = __expf(fminf(lrelu(av.w + dv.w + eav*ce.w), 70.f));
    float4 st; st.x = p0; st.y = p1; st.z = p2; st.w = p3;
    *(float4*)&g_ealpha[e*4] = st;
    red_add_v4(&g_s[d*4], p0, p1, p2, p3);
}
__global__ void k_gat_init() {
    int idx = blockIdx.x*256 + threadIdx.x;   // NN*64
    int i = idx >> 6, h = (idx >> 4) & 3;
    g_agg[idx] = g_xg[idx] * g_eself[i*4+h] / (g_s[i*4+h] + 1e-16f);
}
__global__ void k_gatB(const int* __restrict__ ei) {
    int idx = blockIdx.x*256 + threadIdx.x;   // EE*16
    int e = idx >> 4, ch = idx & 15, h = ch >> 2;
    int s = ei[e], d = ei[EE+e];
    float coef = g_ealpha[e*4+h] / (g_s[d*4+h] + 1e-16f);
    float4 v = *(const float4*)&g_xg[s*64 + ch*4];
    red_add_v4(&g_agg[d*64 + ch*4], v.x*coef, v.y*coef, v.z*coef, v.w*coef);
}
__global__ void k_postgat(const float* __restrict__ bg, float* __restrict__ xout) {
    int idx = blockIdx.x*256 + threadIdx.x;   // NN*64
    int c = idx & 63;
    float* o = xout ? xout : g_xcur;
    o[idx] = siluf(g_agg[idx] + bg[c]) + g_xln[idx];
}

// ---------------- launch ----------------
extern "C" void kernel_launch(void* const* d_in, const int* in_sizes, int n_in,
                              void* d_out, int out_size) {
    (void)in_sizes; (void)n_in; (void)out_size;
    const float* x  = (const float*)d_in[0];
    const int*   ei = (const int*)  d_in[1];
    const float* ew = (const float*)d_in[2];
    const float* ea = (const float*)d_in[3];

    k_zero<<<1,1>>>();
    k_easum<<<1024,256>>>(ea);

    for (int L = 0; L < 2; L++) {
        const float* gw  = (const float*)d_in[4+12*L+0];
        const float* gb  = (const float*)d_in[4+12*L+1];
        const float* rw  = (const float*)d_in[4+12*L+2];
        const float* rb  = (const float*)d_in[4+12*L+3];
        const float* lg  = (const float*)d_in[4+12*L+4];
        const float* lb  = (const float*)d_in[4+12*L+5];
        const float* Wg  = (const float*)d_in[4+12*L+6];
        const float* bg  = (const float*)d_in[4+12*L+7];
        const float* asv = (const float*)d_in[4+12*L+8];
        const float* adv = (const float*)d_in[4+12*L+9];
        const float* aev = (const float*)d_in[4+12*L+10];
        const float* eww = (const float*)d_in[4+12*L+11];

        const float* xin  = (L == 0) ? x : nullptr;          // null -> g_xcur
        float*       xout = (L == 1) ? (float*)d_out : nullptr; // null -> g_xcur

        // GCN branch + residual
        k_gemm_dual<<<1563,256>>>(xin, gw, rw, rb);
        k_deg_init<<<196,256>>>();
        k_deg_edge<<<3125,256>>>(ei, ew);
        k_dinv<<<196,256>>>();
        k_gcn_init<<<12500,256>>>();
        k_gcn_edge<<<50000,256>>>(ei, ew);
        k_ln<<<6250,256>>>(gb, lg, lb);

        // GAT branch
        k_gemm_gat<<<782,256>>>(Wg);
        k_attdots<<<6250,256>>>(asv, adv);
        k_ce<<<1,32>>>(eww, aev);
        k_sinit<<<782,256>>>();
        k_gatA<<<3125,256>>>(ei, ea);
        k_gat_init<<<12500,256>>>();
        k_gatB<<<50000,256>>>(ei);
        k_postgat<<<12500,256>>>(bg, xout);
    }
}

// round 2
// speedup vs baseline: 1.2549x; 1.2549x over previous
#include <cuda_runtime.h>

#define NN 50000
#define EE 800000
#define FULL 0xffffffffu

// ---------------- scratch (static device globals; no allocs) ----------------
static __device__ float g_h[NN*64];      // GCN-transformed features
static __device__ float g_res[NN*64];    // residual branch
static __device__ float g_xln[NN*64];    // post-GCN layernorm output
static __device__ float g_xg[NN*64];     // GAT-transformed features
static __device__ float g_xcur[NN*64];   // layer-0 output
static __device__ float g_deg[NN];
static __device__ float g_dinv[NN];
static __device__ int   g_cnt[NN];       // in-degree counts (edges only)
static __device__ int   g_ps[NN];        // inclusive scan scratch
static __device__ int   g_blk[128];      // block sums
static __device__ int   g_blkoff[128];
static __device__ int   g_rowptr[NN+1];
static __device__ int   g_cur[NN];
static __device__ int   g_csrc[EE];      // CSR source node per slot
static __device__ float g_cw[EE];        // CSR gcn norm weight per slot
static __device__ int   g_cpos[EE];      // edge id -> CSR slot
static __device__ float g_as[NN*4];
static __device__ float g_ad[NN*4];
static __device__ float g_ep[EE*4];      // exp(alpha) per CSR slot, 4 heads
static __device__ float g_ce[8];         // [0..3]=ce per head, [4]=mean(edge_attr)
static __device__ float g_easum;

// ---------------- helpers ----------------
__device__ __forceinline__ float siluf(float v) { return v * (1.f / (1.f + __expf(-v))); }
__device__ __forceinline__ float lrelu(float v) { return v >= 0.f ? v : 0.2f * v; }

// ---------------- GEMMs ----------------
// g_h = x@W0, g_res = x@W1 + b1. 32-row tile, 256 threads.
__global__ __launch_bounds__(256) void k_gemm_dual(
    const float* __restrict__ xin, const float* __restrict__ W0,
    const float* __restrict__ W1, const float* __restrict__ b1)
{
    const float* x = xin ? xin : g_xcur;
    __shared__ float xs[32*68];
    __shared__ float ws[2][64*68];
    int t = threadIdx.x;
    int row0 = blockIdx.x * 32;
    for (int i = t; i < 4096; i += 256) {
        int k = i >> 6, c = i & 63;
        ws[0][k*68+c] = W0[i];
        ws[1][k*68+c] = W1[i];
    }
    for (int i = t; i < 2048; i += 256) {
        int r = i >> 6, c = i & 63;
        xs[r*68+c] = (row0 + r < NN) ? x[(row0+r)*64 + c] : 0.f;
    }
    __syncthreads();
    int rg = t >> 4, g = t & 15, m = g >> 3, cb = (g & 7) * 8;
    const float* wp = ws[m];
    int r0 = rg*2, r1 = r0 + 1;
    float a0[8], a1[8];
    #pragma unroll
    for (int j = 0; j < 8; j++) { a0[j] = 0.f; a1[j] = 0.f; }
    #pragma unroll 16
    for (int k = 0; k < 64; k++) {
        float xv0 = xs[r0*68+k], xv1 = xs[r1*68+k];
        float w[8];
        *(float4*)&w[0] = *(const float4*)&wp[k*68+cb];
        *(float4*)&w[4] = *(const float4*)&wp[k*68+cb+4];
        #pragma unroll
        for (int j = 0; j < 8; j++) { a0[j] += xv0 * w[j]; a1[j] += xv1 * w[j]; }
    }
    float* y = m ? g_res : g_h;
    if (m) {
        #pragma unroll
        for (int j = 0; j < 8; j++) { float b = b1[cb+j]; a0[j] += b; a1[j] += b; }
    }
    if (row0 + r0 < NN) {
        *(float4*)&y[(row0+r0)*64+cb]   = *(float4*)&a0[0];
        *(float4*)&y[(row0+r0)*64+cb+4] = *(float4*)&a0[4];
    }
    if (row0 + r1 < NN) {
        *(float4*)&y[(row0+r1)*64+cb]   = *(float4*)&a1[0];
        *(float4*)&y[(row0+r1)*64+cb+4] = *(float4*)&a1[4];
    }
}

// g_xg = g_xln @ W ; fused attention dots g_as/g_ad. 64-row tile, 256 threads.
__global__ __launch_bounds__(256) void k_gemm_gat(
    const float* __restrict__ W,
    const float* __restrict__ asrc, const float* __restrict__ adst)
{
    __shared__ float xs[64*68];
    __shared__ float ws[64*68];
    int t = threadIdx.x;
    int row0 = blockIdx.x * 64;
    for (int i = t; i < 4096; i += 256) {
        int k = i >> 6, c = i & 63;
        ws[k*68+c] = W[i];
    }
    for (int i = t; i < 4096; i += 256) {
        int r = i >> 6, c = i & 63;
        xs[r*68+c] = (row0 + r < NN) ? g_xln[(row0+r)*64 + c] : 0.f;
    }
    __syncthreads();
    int rg = t >> 3, cb = (t & 7) * 8;
    int r0 = rg*2, r1 = r0 + 1;
    float a0[8], a1[8];
    #pragma unroll
    for (int j = 0; j < 8; j++) { a0[j] = 0.f; a1[j] = 0.f; }
    #pragma unroll 16
    for (int k = 0; k < 64; k++) {
        float xv0 = xs[r0*68+k], xv1 = xs[r1*68+k];
        float w[8];
        *(float4*)&w[0] = *(const float4*)&ws[k*68+cb];
        *(float4*)&w[4] = *(const float4*)&ws[k*68+cb+4];
        #pragma unroll
        for (int j = 0; j < 8; j++) { a0[j] += xv0 * w[j]; a1[j] += xv1 * w[j]; }
    }
    if (row0 + r0 < NN) {
        *(float4*)&g_xg[(row0+r0)*64+cb]   = *(float4*)&a0[0];
        *(float4*)&g_xg[(row0+r0)*64+cb+4] = *(float4*)&a0[4];
    }
    if (row0 + r1 < NN) {
        *(float4*)&g_xg[(row0+r1)*64+cb]   = *(float4*)&a1[0];
        *(float4*)&g_xg[(row0+r1)*64+cb+4] = *(float4*)&a1[4];
    }
    // fused attention dots: thread pair (t, t^1) covers one head (16 cols)
    float s0 = 0.f, s1 = 0.f, d0 = 0.f, d1 = 0.f;
    #pragma unroll
    for (int j = 0; j < 8; j++) {
        float av = asrc[cb+j], dv = adst[cb+j];
        s0 += a0[j]*av; d0 += a0[j]*dv;
        s1 += a1[j]*av; d1 += a1[j]*dv;
    }
    s0 += __shfl_xor_sync(FULL, s0, 1);
    s1 += __shfl_xor_sync(FULL, s1, 1);
    d0 += __shfl_xor_sync(FULL, d0, 1);
    d1 += __shfl_xor_sync(FULL, d1, 1);
    if ((t & 1) == 0) {
        int hh = cb >> 4;
        if (row0 + r0 < NN) { g_as[(row0+r0)*4+hh] = s0; g_ad[(row0+r0)*4+hh] = d0; }
        if (row0 + r1 < NN) { g_as[(row0+r1)*4+hh] = s1; g_ad[(row0+r1)*4+hh] = d1; }
    }
}

// ---------------- graph setup (once per call) ----------------
__global__ void k_zero() { g_easum = 0.f; }
__global__ void k_easum(const float* __restrict__ ea) {
    __shared__ float ss[8];
    float sum = 0.f;
    for (int i = blockIdx.x*blockDim.x + threadIdx.x; i < EE; i += gridDim.x*blockDim.x)
        sum += ea[i];
    #pragma unroll
    for (int o = 16; o; o >>= 1) sum += __shfl_xor_sync(FULL, sum, o);
    if ((threadIdx.x & 31) == 0) ss[threadIdx.x >> 5] = sum;
    __syncthreads();
    if (threadIdx.x < 8) {
        float v = ss[threadIdx.x];
        #pragma unroll
        for (int o = 4; o; o >>= 1) v += __shfl_xor_sync(0xffu, v, o);
        if (threadIdx.x == 0) atomicAdd(&g_easum, v);
    }
}
__global__ void k_deg_init() {
    int i = blockIdx.x*256 + threadIdx.x;
    if (i < NN) { g_deg[i] = 1.f; g_cnt[i] = 0; }
}
__global__ void k_deg_edge(const int* __restrict__ ei, const float* __restrict__ ew) {
    int e = blockIdx.x*256 + threadIdx.x;
    int d = ei[EE+e];
    atomicAdd(&g_deg[d], ew[e]);
    atomicAdd(&g_cnt[d], 1);
}
__global__ void k_dinv() {
    int i = blockIdx.x*256 + threadIdx.x;
    if (i < NN) g_dinv[i] = rsqrtf(g_deg[i]);
}
__global__ __launch_bounds__(512) void k_scan1() {
    __shared__ int sm[512];
    int t = threadIdx.x;
    int idx = blockIdx.x*512 + t;
    int c = (idx < NN) ? g_cnt[idx] : 0;
    sm[t] = c; __syncthreads();
    #pragma unroll
    for (int off = 1; off < 512; off <<= 1) {
        int v = (t >= off) ? sm[t-off] : 0;
        __syncthreads();
        sm[t] += v;
        __syncthreads();
    }
    if (idx < NN) g_ps[idx] = sm[t];
    if (t == 511) g_blk[blockIdx.x] = sm[511];
}
__global__ void k_scan2(int nblk) {
    if (threadIdx.x == 0) {
        int run = 0;
        for (int i = 0; i < nblk; i++) { g_blkoff[i] = run; run += g_blk[i]; }
    }
}
__global__ __launch_bounds__(512) void k_scan3() {
    int idx = blockIdx.x*512 + threadIdx.x;
    if (idx < NN) {
        g_rowptr[idx+1] = g_ps[idx] + g_blkoff[blockIdx.x];
        g_cur[idx] = 0;
        if (idx == 0) g_rowptr[0] = 0;
    }
}
__global__ void k_fill(const int* __restrict__ ei, const float* __restrict__ ew) {
    int e = blockIdx.x*256 + threadIdx.x;
    int s = ei[e], d = ei[EE+e];
    int pos = g_rowptr[d] + atomicAdd(&g_cur[d], 1);
    g_csrc[pos] = s;
    g_cw[pos]   = g_dinv[s] * ew[e] * g_dinv[d];
    g_cpos[e]   = pos;
}

// ---------------- GCN gather + silu + residual + LN (warp per node) ----------------
__global__ __launch_bounds__(256) void k_gcn_ln(
    const float* __restrict__ gb, const float* __restrict__ lg, const float* __restrict__ lb)
{
    int row = blockIdx.x*8 + (threadIdx.x >> 5);
    if (row >= NN) return;
    int lane = threadIdx.x & 31;
    int start = g_rowptr[row], end = g_rowptr[row+1];
    float dv = g_dinv[row];
    float acc0 = g_h[row*64+lane]    * dv * dv;
    float acc1 = g_h[row*64+32+lane] * dv * dv;
    for (int base = start; base < end; base += 32) {
        int j = base + lane;
        int ms  = (j < end) ? g_csrc[j] : 0;
        float mw = (j < end) ? g_cw[j] : 0.f;
        int n = min(32, end - base);
        for (int k = 0; k < n; k++) {
            int s  = __shfl_sync(FULL, ms, k);
            float w = __shfl_sync(FULL, mw, k);
            acc0 += w * g_h[s*64+lane];
            acc1 += w * g_h[s*64+32+lane];
        }
    }
    float v0 = siluf(acc0 + gb[lane])    + g_res[row*64+lane];
    float v1 = siluf(acc1 + gb[lane+32]) + g_res[row*64+32+lane];
    float sum = v0 + v1;
    #pragma unroll
    for (int o = 16; o; o >>= 1) sum += __shfl_xor_sync(FULL, sum, o);
    float mu = sum * (1.f/64.f);
    float d0 = v0 - mu, d1 = v1 - mu;
    float vs = d0*d0 + d1*d1;
    #pragma unroll
    for (int o = 16; o; o >>= 1) vs += __shfl_xor_sync(FULL, vs, o);
    float inv = rsqrtf(vs * (1.f/64.f) + 1e-5f);
    g_xln[row*64+lane]    = d0 * inv * lg[lane]    + lb[lane];
    g_xln[row*64+32+lane] = d1 * inv * lg[lane+32] + lb[lane+32];
}

// ---------------- GAT ----------------
// ce[h] = sum_c We[h*16+c]*a_e[h*16+c]; ce[4] = mean(edge_attr)
__global__ void k_ce(const float* __restrict__ eww, const float* __restrict__ ae) {
    int lane = threadIdx.x;
    float p0 = eww[lane]*ae[lane];
    float p1 = eww[lane+32]*ae[lane+32];
    #pragma unroll
    for (int o = 8; o; o >>= 1) {
        p0 += __shfl_xor_sync(FULL, p0, o);
        p1 += __shfl_xor_sync(FULL, p1, o);
    }
    if ((lane & 15) == 0) {
        g_ce[lane >> 4]       = p0;
        g_ce[2 + (lane >> 4)] = p1;
    }
    if (lane == 0) g_ce[4] = g_easum * (1.f / EE);
}
// edge-parallel: exp(alpha) written CSR-ordered
__global__ void k_gatA(const int* __restrict__ ei, const float* __restrict__ ea) {
    int e = blockIdx.x*256 + threadIdx.x;
    int s = ei[e], d = ei[EE+e];
    float eav = ea[e];
    float4 av = *(const float4*)&g_as[s*4];
    float4 dv = *(const float4*)&g_ad[d*4];
    float4 ce = *(const float4*)&g_ce[0];
    float4 p;
    p.x = __expf(fminf(lrelu(av.x + dv.x + eav*ce.x), 70.f));
    p.y = __expf(fminf(lrelu(av.y + dv.y + eav*ce.y), 70.f));
    p.z = __expf(fminf(lrelu(av.z + dv.z + eav*ce.z), 70.f));
    p.w = __expf(fminf(lrelu(av.w + dv.w + eav*ce.w), 70.f));
    *(float4*)&g_ep[g_cpos[e]*4] = p;
}
// warp-per-node: softmax denom + weighted gather + silu + skip
__global__ __launch_bounds__(256) void k_gat_gather(
    const float* __restrict__ bg, float* __restrict__ xout)
{
    int row = blockIdx.x*8 + (threadIdx.x >> 5);
    if (row >= NN) return;
    int lane = threadIdx.x & 31;
    int start = g_rowptr[row], end = g_rowptr[row+1];
    // self-loop exp(alpha)
    float4 av = *(const float4*)&g_as[row*4];
    float4 dv = *(const float4*)&g_ad[row*4];
    float4 ce = *(const float4*)&g_ce[0];
    float cm = g_ce[4];
    float4 ps;
    ps.x = __expf(fminf(lrelu(av.x + dv.x + cm*ce.x), 70.f));
    ps.y = __expf(fminf(lrelu(av.y + dv.y + cm*ce.y), 70.f));
    ps.z = __expf(fminf(lrelu(av.z + dv.z + cm*ce.z), 70.f));
    ps.w = __expf(fminf(lrelu(av.w + dv.w + cm*ce.w), 70.f));
    // denominator: lane-parallel sum of g_ep
    float s0 = 0.f, s1 = 0.f, s2 = 0.f, s3 = 0.f;
    for (int j = start + lane; j < end; j += 32) {
        float4 p = *(const float4*)&g_ep[j*4];
        s0 += p.x; s1 += p.y; s2 += p.z; s3 += p.w;
    }
    #pragma unroll
    for (int o = 16; o; o >>= 1) {
        s0 += __shfl_xor_sync(FULL, s0, o);
        s1 += __shfl_xor_sync(FULL, s1, o);
        s2 += __shfl_xor_sync(FULL, s2, o);
        s3 += __shfl_xor_sync(FULL, s3, o);
    }
    float i0 = 1.f/(ps.x + s0 + 1e-16f);
    float i1 = 1.f/(ps.y + s1 + 1e-16f);
    float i2 = 1.f/(ps.z + s2 + 1e-16f);
    float i3 = 1.f/(ps.w + s3 + 1e-16f);
    // accumulate: col c=lane uses head lane>>4 (0/1); col c=lane+32 uses head 2+(lane>>4)
    float pa_self = (lane < 16) ? ps.x : ps.y;
    float pb_self = (lane < 16) ? ps.z : ps.w;
    float acc0 = g_xg[row*64+lane]    * pa_self;
    float acc1 = g_xg[row*64+32+lane] * pb_self;
    for (int base = start; base < end; base += 32) {
        int j = base + lane;
        int ms = (j < end) ? g_csrc[j] : 0;
        float4 mp = (j < end) ? *(const float4*)&g_ep[j*4] : make_float4(0.f,0.f,0.f,0.f);
        int n = min(32, end - base);
        for (int k = 0; k < n; k++) {
            int s = __shfl_sync(FULL, ms, k);
            float p0 = __shfl_sync(FULL, mp.x, k);
            float p1 = __shfl_sync(FULL, mp.y, k);
            float p2 = __shfl_sync(FULL, mp.z, k);
            float p3 = __shfl_sync(FULL, mp.w, k);
            float pa = (lane < 16) ? p0 : p1;
            float pb = (lane < 16) ? p2 : p3;
            acc0 += pa * g_xg[s*64+lane];
            acc1 += pb * g_xg[s*64+32+lane];
        }
    }
    float ia = (lane < 16) ? i0 : i1;
    float ib = (lane < 16) ? i2 : i3;
    float* o = xout ? xout : g_xcur;
    o[row*64+lane]    = siluf(acc0*ia + bg[lane])    + g_xln[row*64+lane];
    o[row*64+32+lane] = siluf(acc1*ib + bg[lane+32]) + g_xln[row*64+32+lane];
}

// ---------------- launch ----------------
extern "C" void kernel_launch(void* const* d_in, const int* in_sizes, int n_in,
                              void* d_out, int out_size) {
    (void)in_sizes; (void)n_in; (void)out_size;
    const float* x  = (const float*)d_in[0];
    const int*   ei = (const int*)  d_in[1];
    const float* ew = (const float*)d_in[2];
    const float* ea = (const float*)d_in[3];

    // graph-structure setup (layer-independent)
    k_zero<<<1,1>>>();
    k_easum<<<1024,256>>>(ea);
    k_deg_init<<<196,256>>>();
    k_deg_edge<<<3125,256>>>(ei, ew);
    k_dinv<<<196,256>>>();
    k_scan1<<<98,512>>>();
    k_scan2<<<1,32>>>(98);
    k_scan3<<<98,512>>>();
    k_fill<<<3125,256>>>(ei, ew);

    for (int L = 0; L < 2; L++) {
        const float* gw  = (const float*)d_in[4+12*L+0];
        const float* gb  = (const float*)d_in[4+12*L+1];
        const float* rw  = (const float*)d_in[4+12*L+2];
        const float* rb  = (const float*)d_in[4+12*L+3];
        const float* lg  = (const float*)d_in[4+12*L+4];
        const float* lb  = (const float*)d_in[4+12*L+5];
        const float* Wg  = (const float*)d_in[4+12*L+6];
        const float* bg  = (const float*)d_in[4+12*L+7];
        const float* asv = (const float*)d_in[4+12*L+8];
        const float* adv = (const float*)d_in[4+12*L+9];
        const float* aev = (const float*)d_in[4+12*L+10];
        const float* eww = (const float*)d_in[4+12*L+11];

        const float* xin  = (L == 0) ? x : nullptr;             // null -> g_xcur
        float*       xout = (L == 1) ? (float*)d_out : nullptr; // null -> g_xcur

        k_gemm_dual<<<1563,256>>>(xin, gw, rw, rb);
        k_gcn_ln<<<6250,256>>>(gb, lg, lb);
        k_gemm_gat<<<782,256>>>(Wg, asv, adv);
        k_ce<<<1,32>>>(eww, aev);
        k_gatA<<<3125,256>>>(ei, ea);
        k_gat_gather<<<6250,256>>>(bg, xout);
    }
}